// round 1
// baseline (speedup 1.0000x reference)
#include <cuda_runtime.h>

// ---------------- problem constants ----------------
#define BB 32
#define NN 207
#define TT 24
#define EE 128
#define HH 8
#define HD 16
#define DMOUT 64
#define MM 32

#define PER_P (NN * EE * EE)              // 3,391,488 floats per projection matrix set
#define OUT_N (BB * NN * TT * DMOUT)      // 10,174,464
#define ATTN_N (BB * NN * HH * TT * TT)   // 30,523,392

// scratch: P_q, P_k, P_v  (3 x 207 x 128 x 128 fp32 = 40.7 MB, L2-resident)
__device__ float g_P[3 * PER_P];

// ---------------- kernel 1: P = p1 @ p2 (per node, flat layout == (N,E,E)) ----------------
__global__ void compute_P_kernel(const float* __restrict__ qp1, const float* __restrict__ qp2,
                                 const float* __restrict__ kp1, const float* __restrict__ kp2,
                                 const float* __restrict__ vp1, const float* __restrict__ vp2) {
    const int per4 = PER_P / 4;           // 847,872 float4 outputs per matrix
    int idx = blockIdx.x * blockDim.x + threadIdx.x;
    if (idx >= 3 * per4) return;
    int m = idx / per4;
    int rem = idx - m * per4;
    int r = rem >> 6;                      // row in (N*64) = 13248
    int c4 = rem & 63;                     // float4 column of 256
    const float* p1 = (m == 0) ? qp1 : ((m == 1) ? kp1 : vp1);
    const float* p2 = (m == 0) ? qp2 : ((m == 1) ? kp2 : vp2);
    const float* p1r = p1 + r * MM;
    float4 acc = make_float4(0.f, 0.f, 0.f, 0.f);
#pragma unroll
    for (int j = 0; j < MM; j++) {
        float a = p1r[j];
        float4 b = reinterpret_cast<const float4*>(p2 + j * 256)[c4];
        acc.x += a * b.x; acc.y += a * b.y; acc.z += a * b.z; acc.w += a * b.w;
    }
    reinterpret_cast<float4*>(g_P + (size_t)m * PER_P + (size_t)r * 256)[c4] = acc;
}

// ---------------- kernel 2: fused projection + attention + output ----------------
// smem layout (floats)
#define SQ 132                              // padded stride for q/k/v tiles
#define OFF_Q 0
#define OFF_K (TT * SQ)                     // 3168
#define OFF_V (2 * TT * SQ)                 // 6336
#define OFF_X (3 * TT * SQ)                 // 9504 (input staging, reused as sO later)
#define OFF_P (OFF_X + TT * EE)             // 12576 (32x128 P chunk)
#define OFF_W (OFF_P + 32 * EE)             // 16672 (128x64 out_W)
#define OFF_B (OFF_W + EE * DMOUT)          // 24864 (bias 64)
#define SMEM_FLOATS (OFF_B + 64)            // 24928 floats = 99,712 bytes
#define OFF_O OFF_X                         // sO[24][128] aliases sX

extern __shared__ float smem[];

__global__ __launch_bounds__(256, 2) void fused_attn_kernel(
    const float* __restrict__ query, const float* __restrict__ key_,
    const float* __restrict__ value,
    const float* __restrict__ outW, const float* __restrict__ outb,
    float* __restrict__ out, float* __restrict__ attn_out, int write_attn)
{
    const int b = blockIdx.x;
    const int n = blockIdx.y;
    const int tid = threadIdx.x;
    const int w = tid >> 5;       // warp 0..7
    const int lane = tid & 31;
    const long bn = (long)b * NN + n;

    // stage out_W (+bias) into smem
    {
        const float4* Wg = reinterpret_cast<const float4*>(outW);
        float4* Ws = reinterpret_cast<float4*>(smem + OFF_W);
        for (int i = tid; i < (EE * DMOUT) / 4; i += 256) Ws[i] = Wg[i];
        if (tid < DMOUT) smem[OFF_B + tid] = outb[tid];
    }

    // ---- three projections: q/k/v = relu(x @ P_n) ----
    for (int m = 0; m < 3; m++) {
        const float* src = ((m == 0) ? query : ((m == 1) ? key_ : value)) + bn * (TT * EE);
        __syncthreads();  // previous consumers of sX/sP done
        {
            const float4* xg = reinterpret_cast<const float4*>(src);
            float4* xs = reinterpret_cast<float4*>(smem + OFF_X);
            for (int i = tid; i < (TT * EE) / 4; i += 256) xs[i] = xg[i];
        }
        float acc[3][4];
#pragma unroll
        for (int r = 0; r < 3; r++)
#pragma unroll
            for (int c = 0; c < 4; c++) acc[r][c] = 0.f;

        const float* Pg = g_P + (size_t)m * PER_P + (size_t)n * EE * EE;
        for (int kb = 0; kb < 4; kb++) {
            __syncthreads();
            {
                const float4* pg = reinterpret_cast<const float4*>(Pg + kb * 32 * EE);
                float4* ps = reinterpret_cast<float4*>(smem + OFF_P);
                for (int i = tid; i < (32 * EE) / 4; i += 256) ps[i] = pg[i];
            }
            __syncthreads();
#pragma unroll
            for (int kk = 0; kk < 32; kk++) {
                float4 bv = reinterpret_cast<float4*>(smem + OFF_P + kk * EE)[lane];
                float a0 = smem[OFF_X + (w * 3 + 0) * EE + kb * 32 + kk];
                float a1 = smem[OFF_X + (w * 3 + 1) * EE + kb * 32 + kk];
                float a2 = smem[OFF_X + (w * 3 + 2) * EE + kb * 32 + kk];
                acc[0][0] += a0 * bv.x; acc[0][1] += a0 * bv.y; acc[0][2] += a0 * bv.z; acc[0][3] += a0 * bv.w;
                acc[1][0] += a1 * bv.x; acc[1][1] += a1 * bv.y; acc[1][2] += a1 * bv.z; acc[1][3] += a1 * bv.w;
                acc[2][0] += a2 * bv.x; acc[2][1] += a2 * bv.y; acc[2][2] += a2 * bv.z; acc[2][3] += a2 * bv.w;
            }
        }
        float* dst = smem + ((m == 0) ? OFF_Q : ((m == 1) ? OFF_K : OFF_V));
#pragma unroll
        for (int r = 0; r < 3; r++) {
            int t = w * 3 + r;
#pragma unroll
            for (int c = 0; c < 4; c++)
                dst[t * SQ + lane * 4 + c] = fmaxf(acc[r][c], 0.f);
        }
    }
    __syncthreads();  // q/k/v complete; sX/sP free (sO aliases)

    // ---- attention: warp w = head h; lane t = query row ----
    {
        const int h = w;
        const int t = lane;
        if (t < TT) {
            float qr[HD];
#pragma unroll
            for (int e = 0; e < HD; e++) qr[e] = smem[OFF_Q + t * SQ + h * HD + e];

            float sc[TT];
#pragma unroll
            for (int s = 0; s < TT; s++) {
                float a = 0.f;
#pragma unroll
                for (int e = 0; e < HD; e++)
                    a += qr[e] * smem[OFF_K + s * SQ + h * HD + e];
                sc[s] = a;
            }
            const float scale = 0.25f;  // 1/sqrt(16)
            float mx = -1e30f;
#pragma unroll
            for (int s = 0; s < TT; s++)
                if (s <= t) mx = fmaxf(mx, sc[s] * scale);
            float sum = 0.f;
            float pr[TT];
#pragma unroll
            for (int s = 0; s < TT; s++) {
                float p = (s <= t) ? expf(sc[s] * scale - mx) : 0.f;
                pr[s] = p;
                sum += p;
            }
            float inv = 1.f / sum;
#pragma unroll
            for (int s = 0; s < TT; s++) pr[s] *= inv;

            // attn @ v  -> sO[t][h*16 + d]
#pragma unroll
            for (int d = 0; d < HD; d++) {
                float a = 0.f;
#pragma unroll
                for (int s = 0; s < TT; s++)
                    a += pr[s] * smem[OFF_V + s * SQ + h * HD + d];
                smem[OFF_O + t * EE + h * HD + d] = a;
            }

            if (write_attn) {
                float* ab = attn_out + (((bn * HH) + h) * TT + t) * TT;
#pragma unroll
                for (int s4 = 0; s4 < TT / 4; s4++) {
                    float4 v4 = make_float4(pr[4 * s4], pr[4 * s4 + 1], pr[4 * s4 + 2], pr[4 * s4 + 3]);
                    reinterpret_cast<float4*>(ab)[s4] = v4;
                }
            }
        }
    }
    __syncthreads();  // sO complete across all heads

    // ---- output projection: out = relu(sO @ W + b), (24x128)@(128x64) ----
    {
        float facc[3][2];
#pragma unroll
        for (int r = 0; r < 3; r++) { facc[r][0] = 0.f; facc[r][1] = 0.f; }
#pragma unroll 4
        for (int i = 0; i < EE; i++) {
            float2 wv = *reinterpret_cast<const float2*>(smem + OFF_W + i * DMOUT + 2 * lane);
            float a0 = smem[OFF_O + (w * 3 + 0) * EE + i];
            float a1 = smem[OFF_O + (w * 3 + 1) * EE + i];
            float a2 = smem[OFF_O + (w * 3 + 2) * EE + i];
            facc[0][0] += a0 * wv.x; facc[0][1] += a0 * wv.y;
            facc[1][0] += a1 * wv.x; facc[1][1] += a1 * wv.y;
            facc[2][0] += a2 * wv.x; facc[2][1] += a2 * wv.y;
        }
        float b0 = smem[OFF_B + 2 * lane];
        float b1 = smem[OFF_B + 2 * lane + 1];
#pragma unroll
        for (int r = 0; r < 3; r++) {
            int t = w * 3 + r;
            float* op = out + ((bn * TT) + t) * DMOUT + 2 * lane;
            float2 res = make_float2(fmaxf(facc[r][0] + b0, 0.f), fmaxf(facc[r][1] + b1, 0.f));
            *reinterpret_cast<float2*>(op) = res;
        }
    }
}

// ---------------- launch ----------------
extern "C" void kernel_launch(void* const* d_in, const int* in_sizes, int n_in,
                              void* d_out, int out_size) {
    const float* query = (const float*)d_in[0];
    const float* key_  = (const float*)d_in[1];
    const float* value = (const float*)d_in[2];
    // d_in[3] = atten_mask (causal triu, recomputed analytically in-kernel)
    const float* qp1 = (const float*)d_in[4];
    const float* qp2 = (const float*)d_in[5];
    const float* kp1 = (const float*)d_in[6];
    const float* kp2 = (const float*)d_in[7];
    const float* vp1 = (const float*)d_in[8];
    const float* vp2 = (const float*)d_in[9];
    const float* outW = (const float*)d_in[10];
    const float* outb = (const float*)d_in[11];
    // d_in[12] = num_heads (fixed 8)

    float* out = (float*)d_out;
    int write_attn = (out_size >= OUT_N + ATTN_N) ? 1 : 0;

    cudaFuncSetAttribute(fused_attn_kernel,
                         cudaFuncAttributeMaxDynamicSharedMemorySize,
                         SMEM_FLOATS * (int)sizeof(float));

    int totalP4 = 3 * (PER_P / 4);
    compute_P_kernel<<<(totalP4 + 255) / 256, 256>>>(qp1, qp2, kp1, kp2, vp1, vp2);

    dim3 grid(BB, NN);
    fused_attn_kernel<<<grid, 256, SMEM_FLOATS * sizeof(float)>>>(
        query, key_, value, outW, outb, out, out + OUT_N, write_attn);
}

// round 3
// speedup vs baseline: 1.6991x; 1.6991x over previous
#include <cuda_runtime.h>
#include <cuda_bf16.h>
#include <cstdint>

// ---------------- problem constants ----------------
#define BB 32
#define NN 207
#define TT 24
#define EE 128
#define HH 8
#define HD 16
#define DMOUT 64
#define MM 32

#define OUT_N (BB * NN * TT * DMOUT)      // 10,174,464
#define ATTN_N (BB * NN * HH * TT * TT)   // 30,523,392

#define ROWS_TOT (BB * TT)                // 768 rows per (n, matrix)
#define MTILE 64
#define NTILES (ROWS_TOT / MTILE)         // 12

// Pt images: per (m,n): [hi 32KB][lo 32KB] bf16, pre-swizzled for direct smem copy
__device__ __align__(16) __nv_bfloat16 g_Pimg[(size_t)3 * NN * 32768];
// projected q/k/v, fp32, layout (B,N,T,E)
__device__ float g_Y[3][(size_t)BB * NN * TT * EE];

// ---------------- helpers ----------------
__device__ __forceinline__ uint32_t smem_u32(const void* p) {
    uint32_t a;
    asm("{ .reg .u64 t; cvta.to.shared.u64 t, %1; cvt.u32.u64 %0, t; }" : "=r"(a) : "l"(p));
    return a;
}
// swizzled byte offset within a [rows x 128 bf16] image: 256B rows, 16B chunks ci 0..15
__device__ __forceinline__ uint32_t sw_off(int r, int ci) {
    return (uint32_t)r * 256u + (uint32_t)((ci ^ (r & 7)) << 4);
}
__device__ __forceinline__ void ldsm_x4(uint32_t* r, uint32_t addr) {
    asm volatile("ldmatrix.sync.aligned.m8n8.x4.shared.b16 {%0,%1,%2,%3}, [%4];"
                 : "=r"(r[0]), "=r"(r[1]), "=r"(r[2]), "=r"(r[3]) : "r"(addr));
}
__device__ __forceinline__ void ldsm_x4_t(uint32_t* r, uint32_t addr) {
    asm volatile("ldmatrix.sync.aligned.m8n8.x4.trans.shared.b16 {%0,%1,%2,%3}, [%4];"
                 : "=r"(r[0]), "=r"(r[1]), "=r"(r[2]), "=r"(r[3]) : "r"(addr));
}
__device__ __forceinline__ void mma_bf16(float* d, const uint32_t* a, const uint32_t* b) {
    asm volatile("mma.sync.aligned.m16n8k16.row.col.f32.bf16.bf16.f32 "
                 "{%0,%1,%2,%3}, {%4,%5,%6,%7}, {%8,%9}, {%0,%1,%2,%3};"
                 : "+f"(d[0]), "+f"(d[1]), "+f"(d[2]), "+f"(d[3])
                 : "r"(a[0]), "r"(a[1]), "r"(a[2]), "r"(a[3]), "r"(b[0]), "r"(b[1]));
}

// ---------------- kernel 0: P images (transposed?, no: B = P[k][c], hi/lo split, swizzled) ----------------
// P_n[k][c] = (p1@p2)[n*64 + k/2][(k&1)*128 + c]
__global__ void prep_P_kernel(const float* __restrict__ qp1, const float* __restrict__ qp2,
                              const float* __restrict__ kp1, const float* __restrict__ kp2,
                              const float* __restrict__ vp1, const float* __restrict__ vp2) {
    extern __shared__ float sm0[];
    float* sp1 = sm0;                                  // 64x32
    float* sp2 = sm0 + 2048;                           // 32x256
    __nv_bfloat16* img = (__nv_bfloat16*)(sm0 + 2048 + 8192);  // hi 16384 + lo 16384 bf16

    const int n = blockIdx.x, m = blockIdx.y, tid = threadIdx.x;
    const float* p1 = (m == 0) ? qp1 : ((m == 1) ? kp1 : vp1);
    const float* p2 = (m == 0) ? qp2 : ((m == 1) ? kp2 : vp2);

    const float4* p1g = (const float4*)(p1 + (size_t)n * 64 * MM);
    for (int i = tid; i < 512; i += 256) ((float4*)sp1)[i] = p1g[i];
    for (int i = tid; i < 2048; i += 256) ((float4*)sp2)[i] = ((const float4*)p2)[i];
    __syncthreads();

    for (int it = 0; it < 64; it++) {
        int idx = it * 256 + tid;
        int c = idx & 127, k = idx >> 7;
        const float* a = sp1 + (k >> 1) * MM;
        const float* bc = sp2 + (k & 1) * 128 + c;
        float acc = 0.f;
#pragma unroll
        for (int j = 0; j < MM; j++) acc += a[j] * bc[j * 256];
        __nv_bfloat16 hi = __float2bfloat16(acc);
        __nv_bfloat16 lo = __float2bfloat16(acc - __bfloat162float(hi));
        uint32_t e = (sw_off(k, c >> 3) + (uint32_t)(c & 7) * 2u) >> 1;  // bf16 elem idx
        img[e] = hi;
        img[16384 + e] = lo;
    }
    __syncthreads();
    float4* dst = (float4*)(g_Pimg + (size_t)(m * NN + n) * 32768);
    const float4* src = (const float4*)img;
    for (int i = tid; i < 4096; i += 256) dst[i] = src[i];
}

// ---------------- kernel 1: projection GEMM via mma.sync bf16 (3-pass split) ----------------
// block = (row-tile of 64, node n, matrix m): C[64x128] = X @ P_n, relu -> g_Y
// smem: [sAh 16K][sAl 16K][sBh 32K][sBl 32K] = 96KB
__global__ __launch_bounds__(128, 2) void proj_mma_kernel(
    const float* __restrict__ query, const float* __restrict__ key_, const float* __restrict__ value) {
    extern __shared__ char smb[];
    const uint32_t sbase = smem_u32(smb);

    const int tile = blockIdx.x, n = blockIdx.y, m = blockIdx.z;
    const int tid = threadIdx.x, wid = tid >> 5, lane = tid & 31;
    const int wr = wid >> 1, wc = wid & 1;           // warp grid 2(M) x 2(N)
    const int grp = lane >> 2, tid4 = lane & 3;

    const float* x = (m == 0) ? query : ((m == 1) ? key_ : value);

    // ---- load A: 64 rows x 128 fp32 -> bf16 hi/lo swizzled ----
#pragma unroll
    for (int it = 0; it < 16; it++) {
        int idx = it * 128 + tid;                    // float4 index, 2048 total
        int r = idx >> 5, c4 = idx & 31;             // row, float4-col
        int g = tile * MTILE + r;
        int b = g / TT, t = g - b * TT;
        float4 v = *(const float4*)(x + (((size_t)b * NN + n) * TT + t) * EE + 4 * c4);
        __nv_bfloat16 h0 = __float2bfloat16(v.x), h1 = __float2bfloat16(v.y);
        __nv_bfloat16 h2 = __float2bfloat16(v.z), h3 = __float2bfloat16(v.w);
        __nv_bfloat16 l0 = __float2bfloat16(v.x - __bfloat162float(h0));
        __nv_bfloat16 l1 = __float2bfloat16(v.y - __bfloat162float(h1));
        __nv_bfloat16 l2 = __float2bfloat16(v.z - __bfloat162float(h2));
        __nv_bfloat16 l3 = __float2bfloat16(v.w - __bfloat162float(h3));
        uint32_t off = sw_off(r, c4 >> 1) + (uint32_t)(c4 & 1) * 8u;
        uint2 hp, lp;
        hp.x = (uint32_t)__bfloat16_as_ushort(h0) | ((uint32_t)__bfloat16_as_ushort(h1) << 16);
        hp.y = (uint32_t)__bfloat16_as_ushort(h2) | ((uint32_t)__bfloat16_as_ushort(h3) << 16);
        lp.x = (uint32_t)__bfloat16_as_ushort(l0) | ((uint32_t)__bfloat16_as_ushort(l1) << 16);
        lp.y = (uint32_t)__bfloat16_as_ushort(l2) | ((uint32_t)__bfloat16_as_ushort(l3) << 16);
        *(uint2*)(smb + off) = hp;
        *(uint2*)(smb + 16384 + off) = lp;
    }
    // ---- copy B images (64KB, pre-swizzled) ----
    {
        const float4* bs = (const float4*)(g_Pimg + (size_t)(m * NN + n) * 32768);
        float4* bd = (float4*)(smb + 32768);
#pragma unroll
        for (int i = tid; i < 4096; i += 128) bd[i] = bs[i];
    }
    __syncthreads();

    float acc[2][8][4];
#pragma unroll
    for (int mr = 0; mr < 2; mr++)
#pragma unroll
        for (int nt = 0; nt < 8; nt++)
#pragma unroll
            for (int i = 0; i < 4; i++) acc[mr][nt][i] = 0.f;

    const int lq = lane & 7, qq = lane >> 3;
    const uint32_t Aoffs[3] = {0u, 16384u, 0u};
    const uint32_t Boffs[3] = {32768u, 32768u, 65536u};

#pragma unroll
    for (int pass = 0; pass < 3; pass++) {
        const uint32_t aBase = sbase + Aoffs[pass];
        const uint32_t bBase = sbase + Boffs[pass];
#pragma unroll
        for (int kc = 0; kc < 8; kc++) {
            uint32_t a[2][4];
#pragma unroll
            for (int mr = 0; mr < 2; mr++) {
                int r = wr * 32 + mr * 16 + lq + (qq & 1) * 8;
                int ci = kc * 2 + (qq >> 1);
                ldsm_x4(a[mr], aBase + sw_off(r, ci));
            }
            uint32_t bfr[8][2];
#pragma unroll
            for (int p = 0; p < 4; p++) {
                int r = kc * 16 + lq + (qq & 1) * 8;
                int ci = wc * 8 + p * 2 + (qq >> 1);
                uint32_t t4[4];
                ldsm_x4_t(t4, bBase + sw_off(r, ci));
                bfr[2 * p][0] = t4[0]; bfr[2 * p][1] = t4[1];
                bfr[2 * p + 1][0] = t4[2]; bfr[2 * p + 1][1] = t4[3];
            }
#pragma unroll
            for (int mr = 0; mr < 2; mr++)
#pragma unroll
                for (int nt = 0; nt < 8; nt++)
                    mma_bf16(acc[mr][nt], a[mr], bfr[nt]);
        }
    }

    // ---- epilogue: relu -> g_Y ----
#pragma unroll
    for (int mr = 0; mr < 2; mr++) {
#pragma unroll
        for (int half = 0; half < 2; half++) {
            int rl = wr * 32 + mr * 16 + grp + half * 8;
            int g = tile * MTILE + rl;
            int b = g / TT, t = g - b * TT;
            float* yb = g_Y[m] + (((size_t)b * NN + n) * TT + t) * EE;
#pragma unroll
            for (int nt = 0; nt < 8; nt++) {
                int col = wc * 64 + nt * 8 + tid4 * 2;
                float2 o = make_float2(fmaxf(acc[mr][nt][half * 2 + 0], 0.f),
                                       fmaxf(acc[mr][nt][half * 2 + 1], 0.f));
                *(float2*)(yb + col) = o;
            }
        }
    }
}

// ---------------- kernel 2: attention + output projection ----------------
#define SQ 132
#define OFF_Q 0
#define OFF_K (TT * SQ)
#define OFF_V (2 * TT * SQ)
#define OFF_O (3 * TT * SQ)
#define OFF_W (OFF_O + TT * EE)
#define OFF_B (OFF_W + EE * DMOUT)
#define SMEM2_FLOATS (OFF_B + 64)

extern __shared__ float sm2[];

__global__ __launch_bounds__(256, 2) void attn_kernel(
    const float* __restrict__ outW, const float* __restrict__ outb,
    float* __restrict__ out, float* __restrict__ attn_out, int write_attn) {
    const int b = blockIdx.x, n = blockIdx.y;
    const int tid = threadIdx.x, w = tid >> 5, lane = tid & 31;
    const long bn = (long)b * NN + n;

    {
        const float4* Wg = (const float4*)outW;
        float4* Ws = (float4*)(sm2 + OFF_W);
        for (int i = tid; i < (EE * DMOUT) / 4; i += 256) Ws[i] = Wg[i];
        if (tid < DMOUT) sm2[OFF_B + tid] = outb[tid];
    }
    for (int m = 0; m < 3; m++) {
        const float4* src = (const float4*)(g_Y[m] + bn * (TT * EE));
        float* dst = sm2 + ((m == 0) ? OFF_Q : ((m == 1) ? OFF_K : OFF_V));
        for (int i = tid; i < (TT * EE) / 4; i += 256) {
            int row = i >> 5, c4 = i & 31;
            *(float4*)(dst + row * SQ + c4 * 4) = src[i];
        }
    }
    __syncthreads();

    {
        const int h = w, t = lane;
        if (t < TT) {
            float qr[HD];
#pragma unroll
            for (int e = 0; e < HD; e++) qr[e] = sm2[OFF_Q + t * SQ + h * HD + e];
            float sc[TT];
#pragma unroll
            for (int s = 0; s < TT; s++) {
                float a = 0.f;
#pragma unroll
                for (int e = 0; e < HD; e++) a += qr[e] * sm2[OFF_K + s * SQ + h * HD + e];
                sc[s] = a;
            }
            const float scale = 0.25f;
            float mx = -1e30f;
#pragma unroll
            for (int s = 0; s < TT; s++) if (s <= t) mx = fmaxf(mx, sc[s] * scale);
            float sum = 0.f, pr[TT];
#pragma unroll
            for (int s = 0; s < TT; s++) {
                float p = (s <= t) ? expf(sc[s] * scale - mx) : 0.f;
                pr[s] = p; sum += p;
            }
            float inv = 1.f / sum;
#pragma unroll
            for (int s = 0; s < TT; s++) pr[s] *= inv;
#pragma unroll
            for (int d = 0; d < HD; d++) {
                float a = 0.f;
#pragma unroll
                for (int s = 0; s < TT; s++) a += pr[s] * sm2[OFF_V + s * SQ + h * HD + d];
                sm2[OFF_O + t * EE + h * HD + d] = a;
            }
            if (write_attn) {
                float* ab = attn_out + (((bn * HH) + h) * TT + t) * TT;
#pragma unroll
                for (int s4 = 0; s4 < TT / 4; s4++)
                    ((float4*)ab)[s4] = make_float4(pr[4 * s4], pr[4 * s4 + 1], pr[4 * s4 + 2], pr[4 * s4 + 3]);
            }
        }
    }
    __syncthreads();

    {
        float facc[3][2];
#pragma unroll
        for (int r = 0; r < 3; r++) { facc[r][0] = 0.f; facc[r][1] = 0.f; }
#pragma unroll 4
        for (int i = 0; i < EE; i++) {
            float2 wv = *(const float2*)(sm2 + OFF_W + i * DMOUT + 2 * lane);
            float a0 = sm2[OFF_O + (w * 3 + 0) * EE + i];
            float a1 = sm2[OFF_O + (w * 3 + 1) * EE + i];
            float a2 = sm2[OFF_O + (w * 3 + 2) * EE + i];
            facc[0][0] += a0 * wv.x; facc[0][1] += a0 * wv.y;
            facc[1][0] += a1 * wv.x; facc[1][1] += a1 * wv.y;
            facc[2][0] += a2 * wv.x; facc[2][1] += a2 * wv.y;
        }
        float b0 = sm2[OFF_B + 2 * lane], b1 = sm2[OFF_B + 2 * lane + 1];
#pragma unroll
        for (int r = 0; r < 3; r++) {
            int t = w * 3 + r;
            float* op = out + ((bn * TT) + t) * DMOUT + 2 * lane;
            *(float2*)op = make_float2(fmaxf(facc[r][0] + b0, 0.f), fmaxf(facc[r][1] + b1, 0.f));
        }
    }
}

// ---------------- launch ----------------
extern "C" void kernel_launch(void* const* d_in, const int* in_sizes, int n_in,
                              void* d_out, int out_size) {
    const float* query = (const float*)d_in[0];
    const float* key_  = (const float*)d_in[1];
    const float* value = (const float*)d_in[2];
    const float* qp1 = (const float*)d_in[4];
    const float* qp2 = (const float*)d_in[5];
    const float* kp1 = (const float*)d_in[6];
    const float* kp2 = (const float*)d_in[7];
    const float* vp1 = (const float*)d_in[8];
    const float* vp2 = (const float*)d_in[9];
    const float* outW = (const float*)d_in[10];
    const float* outb = (const float*)d_in[11];

    float* out = (float*)d_out;
    int write_attn = (out_size >= OUT_N + ATTN_N) ? 1 : 0;

    static int attr_done = 0;
    if (!attr_done) {
        cudaFuncSetAttribute(prep_P_kernel, cudaFuncAttributeMaxDynamicSharedMemorySize, 106496);
        cudaFuncSetAttribute(proj_mma_kernel, cudaFuncAttributeMaxDynamicSharedMemorySize, 98304);
        cudaFuncSetAttribute(attn_kernel, cudaFuncAttributeMaxDynamicSharedMemorySize, SMEM2_FLOATS * (int)sizeof(float));
        attr_done = 1;
    }

    prep_P_kernel<<<dim3(NN, 3), 256, 106496>>>(qp1, qp2, kp1, kp2, vp1, vp2);
    proj_mma_kernel<<<dim3(NTILES, NN, 3), 128, 98304>>>(query, key_, value);
    attn_kernel<<<dim3(BB, NN), 256, SMEM2_FLOATS * sizeof(float)>>>(
        outW, outb, out, out + OUT_N, write_attn);
}

// round 4
// speedup vs baseline: 1.7675x; 1.0403x over previous
#include <cuda_runtime.h>
#include <cuda_bf16.h>
#include <cstdint>

// ---------------- problem constants ----------------
#define BB 32
#define NN 207
#define TT 24
#define EE 128
#define HH 8
#define HD 16
#define DMOUT 64
#define MM 32

#define OUT_N (BB * NN * TT * DMOUT)
#define ATTN_N (BB * NN * HH * TT * TT)

#define ROWS_TOT (BB * TT)                // 768
#define MTILE 64
#define NTILES (ROWS_TOT / MTILE)         // 12

__device__ __align__(16) __nv_bfloat16 g_Pimg[(size_t)3 * NN * 32768];
__device__ float g_Y[3][(size_t)BB * NN * TT * EE];

// ---------------- helpers ----------------
__device__ __forceinline__ uint32_t smem_u32(const void* p) {
    uint32_t a;
    asm("{ .reg .u64 t; cvta.to.shared.u64 t, %1; cvt.u32.u64 %0, t; }" : "=r"(a) : "l"(p));
    return a;
}
__device__ __forceinline__ uint32_t sw_off(int r, int ci) {
    return (uint32_t)r * 256u + (uint32_t)((ci ^ (r & 7)) << 4);
}
__device__ __forceinline__ void ldsm_x4(uint32_t* r, uint32_t addr) {
    asm volatile("ldmatrix.sync.aligned.m8n8.x4.shared.b16 {%0,%1,%2,%3}, [%4];"
                 : "=r"(r[0]), "=r"(r[1]), "=r"(r[2]), "=r"(r[3]) : "r"(addr));
}
__device__ __forceinline__ void ldsm_x4_t(uint32_t* r, uint32_t addr) {
    asm volatile("ldmatrix.sync.aligned.m8n8.x4.trans.shared.b16 {%0,%1,%2,%3}, [%4];"
                 : "=r"(r[0]), "=r"(r[1]), "=r"(r[2]), "=r"(r[3]) : "r"(addr));
}
__device__ __forceinline__ void mma_bf16(float* d, const uint32_t* a, const uint32_t* b) {
    asm volatile("mma.sync.aligned.m16n8k16.row.col.f32.bf16.bf16.f32 "
                 "{%0,%1,%2,%3}, {%4,%5,%6,%7}, {%8,%9}, {%0,%1,%2,%3};"
                 : "+f"(d[0]), "+f"(d[1]), "+f"(d[2]), "+f"(d[3])
                 : "r"(a[0]), "r"(a[1]), "r"(a[2]), "r"(a[3]), "r"(b[0]), "r"(b[1]));
}
#define CP_ASYNC16(dst, src) \
    asm volatile("cp.async.cg.shared.global [%0], [%1], 16;" :: "r"(dst), "l"(src))
#define CP_COMMIT() asm volatile("cp.async.commit_group;")
#define CP_WAIT0()  asm volatile("cp.async.wait_group 0;")

// ---------------- kernel 0: P images (bf16 hi/lo split, pre-swizzled) ----------------
__global__ void prep_P_kernel(const float* __restrict__ qp1, const float* __restrict__ qp2,
                              const float* __restrict__ kp1, const float* __restrict__ kp2,
                              const float* __restrict__ vp1, const float* __restrict__ vp2) {
    extern __shared__ float sm0[];
    float* sp1 = sm0;                                   // 64x32
    float* sp2 = sm0 + 2048;                            // 32x256
    char* img = (char*)(sm0 + 2048 + 8192);             // 64KB: hi 32KB | lo 32KB

    const int n = blockIdx.x, m = blockIdx.y, tid = threadIdx.x;
    const float* p1 = (m == 0) ? qp1 : ((m == 1) ? kp1 : vp1);
    const float* p2 = (m == 0) ? qp2 : ((m == 1) ? kp2 : vp2);

    const float4* p1g = (const float4*)(p1 + (size_t)n * 64 * MM);
    for (int i = tid; i < 512; i += 256) ((float4*)sp1)[i] = p1g[i];
    for (int i = tid; i < 2048; i += 256) ((float4*)sp2)[i] = ((const float4*)p2)[i];
    __syncthreads();

#pragma unroll
    for (int it = 0; it < 16; it++) {
        int idx = it * 256 + tid;              // 4096 float4 jobs
        int c4 = idx & 31, k = idx >> 5;
        const float* a = sp1 + (k >> 1) * MM;
        const float* bb = sp2 + (k & 1) * 128 + 4 * c4;
        float4 acc = make_float4(0.f, 0.f, 0.f, 0.f);
#pragma unroll
        for (int j = 0; j < MM; j++) {
            float aj = a[j];
            float4 bv = *(const float4*)(bb + j * 256);
            acc.x += aj * bv.x; acc.y += aj * bv.y; acc.z += aj * bv.z; acc.w += aj * bv.w;
        }
        __nv_bfloat16 h0 = __float2bfloat16(acc.x), h1 = __float2bfloat16(acc.y);
        __nv_bfloat16 h2 = __float2bfloat16(acc.z), h3 = __float2bfloat16(acc.w);
        __nv_bfloat16 l0 = __float2bfloat16(acc.x - __bfloat162float(h0));
        __nv_bfloat16 l1 = __float2bfloat16(acc.y - __bfloat162float(h1));
        __nv_bfloat16 l2 = __float2bfloat16(acc.z - __bfloat162float(h2));
        __nv_bfloat16 l3 = __float2bfloat16(acc.w - __bfloat162float(h3));
        uint32_t off = sw_off(k, c4 >> 1) + (uint32_t)(c4 & 1) * 8u;
        uint2 hp, lp;
        hp.x = (uint32_t)__bfloat16_as_ushort(h0) | ((uint32_t)__bfloat16_as_ushort(h1) << 16);
        hp.y = (uint32_t)__bfloat16_as_ushort(h2) | ((uint32_t)__bfloat16_as_ushort(h3) << 16);
        lp.x = (uint32_t)__bfloat16_as_ushort(l0) | ((uint32_t)__bfloat16_as_ushort(l1) << 16);
        lp.y = (uint32_t)__bfloat16_as_ushort(l2) | ((uint32_t)__bfloat16_as_ushort(l3) << 16);
        *(uint2*)(img + off) = hp;
        *(uint2*)(img + 32768 + off) = lp;
    }
    __syncthreads();
    float4* dst = (float4*)(g_Pimg + (size_t)(m * NN + n) * 32768);
    const float4* src = (const float4*)img;
    for (int i = tid; i < 4096; i += 256) dst[i] = src[i];
}

// ---------------- kernel 1: projection GEMM via mma.sync (3-pass bf16 split) ----------------
// 256 threads, warp grid 2(M)x4(N). smem: [Ah 16K][Al 16K][Bh 32K][Bl 32K] = 96KB
__global__ __launch_bounds__(256, 2) void proj_mma_kernel(
    const float* __restrict__ query, const float* __restrict__ key_, const float* __restrict__ value) {
    extern __shared__ char smb[];
    const uint32_t sbase = smem_u32(smb);

    const int tile = blockIdx.x, n = blockIdx.y, m = blockIdx.z;
    const int tid = threadIdx.x, wid = tid >> 5, lane = tid & 31;
    const int wr = wid >> 2, wc = wid & 3;           // 2(M) x 4(N)
    const int grp = lane >> 2, tid4 = lane & 3;

    const float* x = (m == 0) ? query : ((m == 1) ? key_ : value);

    // B: async copy 64KB (overlaps A conversion below)
    {
        const char* bs = (const char*)(g_Pimg + (size_t)(m * NN + n) * 32768);
        uint32_t bd = sbase + 32768;
#pragma unroll
        for (int i = tid; i < 4096; i += 256)
            CP_ASYNC16(bd + i * 16, bs + i * 16);
        CP_COMMIT();
    }
    // A: 64 rows x 128 fp32 -> bf16 hi/lo, swizzled
#pragma unroll
    for (int it = 0; it < 8; it++) {
        int idx = it * 256 + tid;                    // 2048 float4 jobs
        int r = idx >> 5, c4 = idx & 31;
        int g = tile * MTILE + r;
        int b = g / TT, t = g - b * TT;
        float4 v = *(const float4*)(x + (((size_t)b * NN + n) * TT + t) * EE + 4 * c4);
        __nv_bfloat16 h0 = __float2bfloat16(v.x), h1 = __float2bfloat16(v.y);
        __nv_bfloat16 h2 = __float2bfloat16(v.z), h3 = __float2bfloat16(v.w);
        __nv_bfloat16 l0 = __float2bfloat16(v.x - __bfloat162float(h0));
        __nv_bfloat16 l1 = __float2bfloat16(v.y - __bfloat162float(h1));
        __nv_bfloat16 l2 = __float2bfloat16(v.z - __bfloat162float(h2));
        __nv_bfloat16 l3 = __float2bfloat16(v.w - __bfloat162float(h3));
        uint32_t off = sw_off(r, c4 >> 1) + (uint32_t)(c4 & 1) * 8u;
        uint2 hp, lp;
        hp.x = (uint32_t)__bfloat16_as_ushort(h0) | ((uint32_t)__bfloat16_as_ushort(h1) << 16);
        hp.y = (uint32_t)__bfloat16_as_ushort(h2) | ((uint32_t)__bfloat16_as_ushort(h3) << 16);
        lp.x = (uint32_t)__bfloat16_as_ushort(l0) | ((uint32_t)__bfloat16_as_ushort(l1) << 16);
        lp.y = (uint32_t)__bfloat16_as_ushort(l2) | ((uint32_t)__bfloat16_as_ushort(l3) << 16);
        *(uint2*)(smb + off) = hp;
        *(uint2*)(smb + 16384 + off) = lp;
    }
    CP_WAIT0();
    __syncthreads();

    float acc[2][4][4];
#pragma unroll
    for (int mr = 0; mr < 2; mr++)
#pragma unroll
        for (int nt = 0; nt < 4; nt++)
#pragma unroll
            for (int i = 0; i < 4; i++) acc[mr][nt][i] = 0.f;

    const int lq = lane & 7, qq = lane >> 3;
    const uint32_t Aoffs[3] = {0u, 16384u, 0u};
    const uint32_t Boffs[3] = {32768u, 32768u, 65536u};

#pragma unroll
    for (int pass = 0; pass < 3; pass++) {
        const uint32_t aBase = sbase + Aoffs[pass];
        const uint32_t bBase = sbase + Boffs[pass];
#pragma unroll
        for (int kc = 0; kc < 8; kc++) {
            uint32_t a[2][4];
#pragma unroll
            for (int mr = 0; mr < 2; mr++) {
                int r = wr * 32 + mr * 16 + lq + (qq & 1) * 8;
                int ci = kc * 2 + (qq >> 1);
                ldsm_x4(a[mr], aBase + sw_off(r, ci));
            }
            uint32_t bfr[4][2];
#pragma unroll
            for (int p = 0; p < 2; p++) {
                int r = kc * 16 + lq + (qq & 1) * 8;
                int ci = wc * 4 + p * 2 + (qq >> 1);
                uint32_t t4[4];
                ldsm_x4_t(t4, bBase + sw_off(r, ci));
                bfr[2 * p][0] = t4[0]; bfr[2 * p][1] = t4[1];
                bfr[2 * p + 1][0] = t4[2]; bfr[2 * p + 1][1] = t4[3];
            }
#pragma unroll
            for (int mr = 0; mr < 2; mr++)
#pragma unroll
                for (int nt = 0; nt < 4; nt++)
                    mma_bf16(acc[mr][nt], a[mr], bfr[nt]);
        }
    }

    // epilogue: relu -> g_Y
#pragma unroll
    for (int mr = 0; mr < 2; mr++) {
#pragma unroll
        for (int half = 0; half < 2; half++) {
            int rl = wr * 32 + mr * 16 + grp + half * 8;
            int g = tile * MTILE + rl;
            int b = g / TT, t = g - b * TT;
            float* yb = g_Y[m] + (((size_t)b * NN + n) * TT + t) * EE;
#pragma unroll
            for (int nt = 0; nt < 4; nt++) {
                int col = wc * 32 + nt * 8 + tid4 * 2;
                *(float2*)(yb + col) = make_float2(fmaxf(acc[mr][nt][half * 2 + 0], 0.f),
                                                   fmaxf(acc[mr][nt][half * 2 + 1], 0.f));
            }
        }
    }
}

// ---------------- kernel 2: attention + output projection (8 batches / block) ----------------
#define SQ 132
#define OFF_Q 0
#define OFF_K (TT * SQ)
#define OFF_V (2 * TT * SQ)
#define OFF_O (3 * TT * SQ)
#define OFF_W (OFF_O + TT * EE)
#define OFF_B (OFF_W + EE * DMOUT)
#define SMEM2_FLOATS (OFF_B + 64)
#define BPB 8                                  // batches per block

extern __shared__ float sm2[];

__global__ __launch_bounds__(256, 2) void attn_kernel(
    const float* __restrict__ outW, const float* __restrict__ outb,
    float* __restrict__ out, float* __restrict__ attn_out, int write_attn) {
    const int n = blockIdx.x;
    const int b0 = blockIdx.y * BPB;
    const int tid = threadIdx.x, w = tid >> 5, lane = tid & 31;

    // stage W + bias once
    {
        const float4* Wg = (const float4*)outW;
        float4* Ws = (float4*)(sm2 + OFF_W);
        for (int i = tid; i < (EE * DMOUT) / 4; i += 256) Ws[i] = Wg[i];
        if (tid < DMOUT) sm2[OFF_B + tid] = outb[tid];
    }

    for (int b = b0; b < b0 + BPB; b++) {
        const long bn = (long)b * NN + n;
        __syncthreads();   // prior iteration fully consumed K/V/O
        for (int m = 0; m < 3; m++) {
            const float4* src = (const float4*)(g_Y[m] + bn * (TT * EE));
            float* dst = sm2 + ((m == 0) ? OFF_Q : ((m == 1) ? OFF_K : OFF_V));
            for (int i = tid; i < (TT * EE) / 4; i += 256) {
                int row = i >> 5, c4 = i & 31;
                *(float4*)(dst + row * SQ + c4 * 4) = src[i];
            }
        }
        __syncthreads();

        // attention: warp = head, lane = query row
        {
            const int h = w, t = lane;
            if (t < TT) {
                float qr[HD];
#pragma unroll
                for (int e = 0; e < HD; e++) qr[e] = sm2[OFF_Q + t * SQ + h * HD + e];
                float sc[TT];
#pragma unroll
                for (int s = 0; s < TT; s++) {
                    float a = 0.f;
#pragma unroll
                    for (int e = 0; e < HD; e++) a += qr[e] * sm2[OFF_K + s * SQ + h * HD + e];
                    sc[s] = a;
                }
                const float scale = 0.25f;
                float mx = -1e30f;
#pragma unroll
                for (int s = 0; s < TT; s++) if (s <= t) mx = fmaxf(mx, sc[s] * scale);
                float sum = 0.f, pr[TT];
#pragma unroll
                for (int s = 0; s < TT; s++) {
                    float p = (s <= t) ? __expf(sc[s] * scale - mx) : 0.f;
                    pr[s] = p; sum += p;
                }
                float inv = 1.f / sum;
#pragma unroll
                for (int s = 0; s < TT; s++) pr[s] *= inv;
#pragma unroll
                for (int d = 0; d < HD; d++) {
                    float a = 0.f;
#pragma unroll
                    for (int s = 0; s < TT; s++) a += pr[s] * sm2[OFF_V + s * SQ + h * HD + d];
                    sm2[OFF_O + t * EE + h * HD + d] = a;
                }
                if (write_attn) {
                    float* ab = attn_out + (((bn * HH) + h) * TT + t) * TT;
#pragma unroll
                    for (int s4 = 0; s4 < TT / 4; s4++)
                        ((float4*)ab)[s4] = make_float4(pr[4 * s4], pr[4 * s4 + 1], pr[4 * s4 + 2], pr[4 * s4 + 3]);
                }
            }
        }
        __syncthreads();

        // output projection
        {
            float facc[3][2];
#pragma unroll
            for (int r = 0; r < 3; r++) { facc[r][0] = 0.f; facc[r][1] = 0.f; }
#pragma unroll 4
            for (int i = 0; i < EE; i++) {
                float2 wv = *(const float2*)(sm2 + OFF_W + i * DMOUT + 2 * lane);
                float a0 = sm2[OFF_O + (w * 3 + 0) * EE + i];
                float a1 = sm2[OFF_O + (w * 3 + 1) * EE + i];
                float a2 = sm2[OFF_O + (w * 3 + 2) * EE + i];
                facc[0][0] += a0 * wv.x; facc[0][1] += a0 * wv.y;
                facc[1][0] += a1 * wv.x; facc[1][1] += a1 * wv.y;
                facc[2][0] += a2 * wv.x; facc[2][1] += a2 * wv.y;
            }
            float bb0 = sm2[OFF_B + 2 * lane], bb1 = sm2[OFF_B + 2 * lane + 1];
#pragma unroll
            for (int r = 0; r < 3; r++) {
                int t = w * 3 + r;
                float* op = out + ((bn * TT) + t) * DMOUT + 2 * lane;
                *(float2*)op = make_float2(fmaxf(facc[r][0] + bb0, 0.f), fmaxf(facc[r][1] + bb1, 0.f));
            }
        }
    }
}

// ---------------- launch ----------------
extern "C" void kernel_launch(void* const* d_in, const int* in_sizes, int n_in,
                              void* d_out, int out_size) {
    const float* query = (const float*)d_in[0];
    const float* key_  = (const float*)d_in[1];
    const float* value = (const float*)d_in[2];
    const float* qp1 = (const float*)d_in[4];
    const float* qp2 = (const float*)d_in[5];
    const float* kp1 = (const float*)d_in[6];
    const float* kp2 = (const float*)d_in[7];
    const float* vp1 = (const float*)d_in[8];
    const float* vp2 = (const float*)d_in[9];
    const float* outW = (const float*)d_in[10];
    const float* outb = (const float*)d_in[11];

    float* out = (float*)d_out;
    int write_attn = (out_size >= OUT_N + ATTN_N) ? 1 : 0;

    static int attr_done = 0;
    if (!attr_done) {
        cudaFuncSetAttribute(prep_P_kernel, cudaFuncAttributeMaxDynamicSharedMemorySize, 106496);
        cudaFuncSetAttribute(proj_mma_kernel, cudaFuncAttributeMaxDynamicSharedMemorySize, 98304);
        cudaFuncSetAttribute(attn_kernel, cudaFuncAttributeMaxDynamicSharedMemorySize, SMEM2_FLOATS * (int)sizeof(float));
        attr_done = 1;
    }

    prep_P_kernel<<<dim3(NN, 3), 256, 106496>>>(qp1, qp2, kp1, kp2, vp1, vp2);
    proj_mma_kernel<<<dim3(NTILES, NN, 3), 256, 98304>>>(query, key_, value);
    attn_kernel<<<dim3(NN, BB / BPB), 256, SMEM2_FLOATS * sizeof(float)>>>(
        outW, outb, out, out + OUT_N, write_attn);
}

// round 5
// speedup vs baseline: 1.8860x; 1.0670x over previous
#include <cuda_runtime.h>
#include <cuda_bf16.h>
#include <cstdint>

// ---------------- problem constants ----------------
#define BB 32
#define NN 207
#define TT 24
#define EE 128
#define HH 8
#define HD 16
#define DMOUT 64
#define MM 32

#define OUT_N (BB * NN * TT * DMOUT)
#define ATTN_N (BB * NN * HH * TT * TT)

// P images: per (m,n): [hi 32KB][lo 32KB] bf16, pre-swizzled (128 k-rows x 256B)
__device__ __align__(16) __nv_bfloat16 g_Pimg[(size_t)3 * NN * 32768];

// ---------------- helpers ----------------
__device__ __forceinline__ uint32_t smem_u32(const void* p) {
    uint32_t a;
    asm("{ .reg .u64 t; cvta.to.shared.u64 t, %1; cvt.u32.u64 %0, t; }" : "=r"(a) : "l"(p));
    return a;
}
// swizzled byte offset inside an image with 256B rows, 16B chunks ci 0..15
__device__ __forceinline__ uint32_t sw_off(int r, int ci) {
    return (uint32_t)r * 256u + (uint32_t)((ci ^ (r & 7)) << 4);
}
__device__ __forceinline__ void ldsm_x4(uint32_t* r, uint32_t addr) {
    asm volatile("ldmatrix.sync.aligned.m8n8.x4.shared.b16 {%0,%1,%2,%3}, [%4];"
                 : "=r"(r[0]), "=r"(r[1]), "=r"(r[2]), "=r"(r[3]) : "r"(addr));
}
__device__ __forceinline__ void ldsm_x4_t(uint32_t* r, uint32_t addr) {
    asm volatile("ldmatrix.sync.aligned.m8n8.x4.trans.shared.b16 {%0,%1,%2,%3}, [%4];"
                 : "=r"(r[0]), "=r"(r[1]), "=r"(r[2]), "=r"(r[3]) : "r"(addr));
}
__device__ __forceinline__ void mma_bf16(float* d, const uint32_t* a, const uint32_t* b) {
    asm volatile("mma.sync.aligned.m16n8k16.row.col.f32.bf16.bf16.f32 "
                 "{%0,%1,%2,%3}, {%4,%5,%6,%7}, {%8,%9}, {%0,%1,%2,%3};"
                 : "+f"(d[0]), "+f"(d[1]), "+f"(d[2]), "+f"(d[3])
                 : "r"(a[0]), "r"(a[1]), "r"(a[2]), "r"(a[3]), "r"(b[0]), "r"(b[1]));
}
#define CP_ASYNC16(dst, src) \
    asm volatile("cp.async.cg.shared.global [%0], [%1], 16;" :: "r"(dst), "l"(src))
#define CP_COMMIT() asm volatile("cp.async.commit_group;")
#define CP_WAIT0()  asm volatile("cp.async.wait_group 0;")

// ---------------- kernel 0: build P images (bf16 hi/lo, swizzled) ----------------
__global__ __launch_bounds__(256, 4) void prep_P_kernel(
    const float* __restrict__ qp1, const float* __restrict__ qp2,
    const float* __restrict__ kp1, const float* __restrict__ kp2,
    const float* __restrict__ vp1, const float* __restrict__ vp2) {
    extern __shared__ float sm0[];
    float* sp1 = sm0;              // 64 x 33 (padded)
    float* sp2 = sm0 + 2112;       // 32 x 256

    const int n = blockIdx.x, m = blockIdx.y, tid = threadIdx.x;
    const float* p1 = (m == 0) ? qp1 : ((m == 1) ? kp1 : vp1);
    const float* p2 = (m == 0) ? qp2 : ((m == 1) ? kp2 : vp2);

    for (int idx = tid; idx < 2048; idx += 256)
        sp1[(idx >> 5) * 33 + (idx & 31)] = p1[(size_t)n * 2048 + idx];
    for (int i = tid; i < 2048; i += 256)
        ((float4*)sp2)[i] = ((const float4*)p2)[i];
    __syncthreads();

    char* gbase = (char*)(g_Pimg + (size_t)(m * NN + n) * 32768);
    const float4* sp2f4 = (const float4*)sp2;
#pragma unroll
    for (int it = 0; it < 16; it++) {
        int idx = it * 256 + tid;                  // 4096 float4 jobs
        int group = idx >> 5, l = idx & 31;
        int c4 = (group & 7) * 4 + (l & 3);        // 0..31
        int k  = (group >> 3) * 8 + (l >> 2);      // 0..127
        const float* a = sp1 + (k >> 1) * 33;
        int boff = (k & 1) * 32 + c4;
        float4 acc = make_float4(0.f, 0.f, 0.f, 0.f);
#pragma unroll
        for (int j = 0; j < 32; j++) {
            float aj = a[j];
            float4 bv = sp2f4[j * 64 + boff];
            acc.x += aj * bv.x; acc.y += aj * bv.y; acc.z += aj * bv.z; acc.w += aj * bv.w;
        }
        __nv_bfloat16 h0 = __float2bfloat16(acc.x), h1 = __float2bfloat16(acc.y);
        __nv_bfloat16 h2 = __float2bfloat16(acc.z), h3 = __float2bfloat16(acc.w);
        __nv_bfloat16 l0 = __float2bfloat16(acc.x - __bfloat162float(h0));
        __nv_bfloat16 l1 = __float2bfloat16(acc.y - __bfloat162float(h1));
        __nv_bfloat16 l2 = __float2bfloat16(acc.z - __bfloat162float(h2));
        __nv_bfloat16 l3 = __float2bfloat16(acc.w - __bfloat162float(h3));
        uint2 hp, lp;
        hp.x = (uint32_t)__bfloat16_as_ushort(h0) | ((uint32_t)__bfloat16_as_ushort(h1) << 16);
        hp.y = (uint32_t)__bfloat16_as_ushort(h2) | ((uint32_t)__bfloat16_as_ushort(h3) << 16);
        lp.x = (uint32_t)__bfloat16_as_ushort(l0) | ((uint32_t)__bfloat16_as_ushort(l1) << 16);
        lp.y = (uint32_t)__bfloat16_as_ushort(l2) | ((uint32_t)__bfloat16_as_ushort(l3) << 16);
        uint32_t off = sw_off(k, c4 >> 1) + (uint32_t)(c4 & 1) * 8u;
        *(uint2*)(gbase + off) = hp;
        *(uint2*)(gbase + 32768 + off) = lp;
    }
}

// ---------------- fused kernel: projections + attention + output ----------------
// smem bytes: [Ah 0..6144)[Al 6144..12288)[Bh 12288..45056)[Bl 45056..77824)[qkv 77824..114976)
// after GEMMs, B region is reused: W @12288 (32KB), bias @45056 (256B), sO @45312 (24x132 f32)
#define SQ 129
#define F_Q 19456
#define F_K (F_Q + TT * SQ)     // 22552
#define F_V (F_K + TT * SQ)     // 25648
#define F_W 3072                 // floats (byte 12288)
#define F_BIAS 11264             // byte 45056
#define F_SO 11328               // byte 45312, stride 132
#define SO 132
#define SMEMF_TOTAL (F_V + TT * SQ)   // 28744 floats = 114976 bytes

__global__ __launch_bounds__(256, 2) void fused_kernel(
    const float* __restrict__ query, const float* __restrict__ key_,
    const float* __restrict__ value,
    const float* __restrict__ outW, const float* __restrict__ outb,
    float* __restrict__ out, float* __restrict__ attn_out, int write_attn) {
    extern __shared__ float smf[];
    char* smb = (char*)smf;
    const uint32_t sbase = smem_u32(smb);

    const int b = blockIdx.x, n = blockIdx.y;
    const int tid = threadIdx.x, wid = tid >> 5, lane = tid & 31;
    const int wr = wid >> 2, wc = wid & 3;        // warp grid 2(M) x 4(N)
    const int grp = lane >> 2, tid4 = lane & 3;
    const int lq = lane & 7, qq = lane >> 3;
    const long bn = (long)b * NN + n;

    // ===== three projections =====
    for (int m = 0; m < 3; m++) {
        if (m) __syncthreads();                   // sA/sB free again
        // B: async copy this matrix's P image (64KB)
        {
            const char* bs = (const char*)(g_Pimg + (size_t)(m * NN + n) * 32768);
            uint32_t bd = sbase + 12288;
#pragma unroll
            for (int i = 0; i < 16; i++) {
                int c = i * 256 + tid;
                CP_ASYNC16(bd + c * 16, bs + c * 16);
            }
            CP_COMMIT();
        }
        // A: 24 rows x 128 fp32 -> bf16 hi/lo swizzled
        {
            const float* x = (m == 0) ? query : ((m == 1) ? key_ : value);
            const float* xb = x + bn * (TT * EE);
#pragma unroll
            for (int it = 0; it < 3; it++) {
                int idx = it * 256 + tid;          // 768 float4 jobs
                int r = idx >> 5, c4 = idx & 31;
                float4 v = *(const float4*)(xb + r * EE + 4 * c4);
                __nv_bfloat16 h0 = __float2bfloat16(v.x), h1 = __float2bfloat16(v.y);
                __nv_bfloat16 h2 = __float2bfloat16(v.z), h3 = __float2bfloat16(v.w);
                __nv_bfloat16 l0 = __float2bfloat16(v.x - __bfloat162float(h0));
                __nv_bfloat16 l1 = __float2bfloat16(v.y - __bfloat162float(h1));
                __nv_bfloat16 l2 = __float2bfloat16(v.z - __bfloat162float(h2));
                __nv_bfloat16 l3 = __float2bfloat16(v.w - __bfloat162float(h3));
                uint2 hp, lp;
                hp.x = (uint32_t)__bfloat16_as_ushort(h0) | ((uint32_t)__bfloat16_as_ushort(h1) << 16);
                hp.y = (uint32_t)__bfloat16_as_ushort(h2) | ((uint32_t)__bfloat16_as_ushort(h3) << 16);
                lp.x = (uint32_t)__bfloat16_as_ushort(l0) | ((uint32_t)__bfloat16_as_ushort(l1) << 16);
                lp.y = (uint32_t)__bfloat16_as_ushort(l2) | ((uint32_t)__bfloat16_as_ushort(l3) << 16);
                uint32_t off = sw_off(r, c4 >> 1) + (uint32_t)(c4 & 1) * 8u;
                *(uint2*)(smb + off) = hp;
                *(uint2*)(smb + 6144 + off) = lp;
            }
        }
        CP_WAIT0();
        __syncthreads();

        // GEMM 24(padded 32) x 128 x 128, 3 passes (AhBh + AlBh + AhBl)
        float acc[4][4];
#pragma unroll
        for (int nt = 0; nt < 4; nt++)
#pragma unroll
            for (int i = 0; i < 4; i++) acc[nt][i] = 0.f;

        const uint32_t Ao[3] = {0u, 6144u, 0u};
        const uint32_t Bo[3] = {12288u, 12288u, 45056u};
#pragma unroll
        for (int pass = 0; pass < 3; pass++) {
            const uint32_t aB = sbase + Ao[pass];
            const uint32_t bB = sbase + Bo[pass];
#pragma unroll
            for (int kc = 0; kc < 8; kc++) {
                uint32_t a[4];
                {
                    int r = wr * 16 + lq + (qq & 1) * 8;   // rows 24..31 = junk, discarded
                    int ci = kc * 2 + (qq >> 1);
                    ldsm_x4(a, aB + sw_off(r, ci));
                }
                uint32_t bf[4][2];
#pragma unroll
                for (int p = 0; p < 2; p++) {
                    int r = kc * 16 + lq + (qq & 1) * 8;
                    int ci = wc * 4 + p * 2 + (qq >> 1);
                    uint32_t t4[4];
                    ldsm_x4_t(t4, bB + sw_off(r, ci));
                    bf[2 * p][0] = t4[0]; bf[2 * p][1] = t4[1];
                    bf[2 * p + 1][0] = t4[2]; bf[2 * p + 1][1] = t4[3];
                }
#pragma unroll
                for (int nt = 0; nt < 4; nt++)
                    mma_bf16(acc[nt], a, bf[nt]);
            }
        }
        // epilogue: relu -> q/k/v smem (stride 129, conflict-free attention reads)
        {
            float* dst = smf + ((m == 0) ? F_Q : ((m == 1) ? F_K : F_V));
#pragma unroll
            for (int half = 0; half < 2; half++) {
                int r = wr * 16 + half * 8 + grp;
                if (r < TT) {
#pragma unroll
                    for (int nt = 0; nt < 4; nt++) {
                        int col = wc * 32 + nt * 8 + tid4 * 2;
                        dst[r * SQ + col]     = fmaxf(acc[nt][half * 2 + 0], 0.f);
                        dst[r * SQ + col + 1] = fmaxf(acc[nt][half * 2 + 1], 0.f);
                    }
                }
            }
        }
    }
    __syncthreads();      // q/k/v complete; B region free

    // W + bias async copy (overlaps attention compute)
    {
        uint32_t wd = sbase + 12288;
        const char* ws = (const char*)outW;
#pragma unroll
        for (int i = 0; i < 8; i++) {
            int c = i * 256 + tid;
            CP_ASYNC16(wd + c * 16, ws + c * 16);
        }
        if (tid < 16) CP_ASYNC16(sbase + 45056 + tid * 16, ((const char*)outb) + tid * 16);
        CP_COMMIT();
    }

    // ===== attention: warp = head, lane = query row =====
    {
        const int h = wid, t = lane;
        if (t < TT) {
            float qr[HD];
#pragma unroll
            for (int e = 0; e < HD; e++) qr[e] = smf[F_Q + t * SQ + h * HD + e];
            float sc[TT];
#pragma unroll
            for (int s = 0; s < TT; s++) {
                float a = 0.f;
#pragma unroll
                for (int e = 0; e < HD; e++) a += qr[e] * smf[F_K + s * SQ + h * HD + e];
                sc[s] = a;
            }
            const float scale = 0.25f;
            float mx = -1e30f;
#pragma unroll
            for (int s = 0; s < TT; s++) if (s <= t) mx = fmaxf(mx, sc[s] * scale);
            float sum = 0.f, pr[TT];
#pragma unroll
            for (int s = 0; s < TT; s++) {
                float p = (s <= t) ? __expf(sc[s] * scale - mx) : 0.f;
                pr[s] = p; sum += p;
            }
            float inv = 1.f / sum;
#pragma unroll
            for (int s = 0; s < TT; s++) pr[s] *= inv;
#pragma unroll
            for (int d = 0; d < HD; d++) {
                float a = 0.f;
#pragma unroll
                for (int s = 0; s < TT; s++) a += pr[s] * smf[F_V + s * SQ + h * HD + d];
                smf[F_SO + t * SO + h * HD + d] = a;
            }
            if (write_attn) {
                float* ab = attn_out + (((bn * HH) + h) * TT + t) * TT;
#pragma unroll
                for (int s4 = 0; s4 < TT / 4; s4++)
                    ((float4*)ab)[s4] = make_float4(pr[4 * s4], pr[4 * s4 + 1], pr[4 * s4 + 2], pr[4 * s4 + 3]);
            }
        }
    }
    CP_WAIT0();
    __syncthreads();      // sO ready (all heads), W ready

    // ===== output projection: out = relu(sO @ W + b) =====
    {
        float facc[3][2];
#pragma unroll
        for (int r = 0; r < 3; r++) { facc[r][0] = 0.f; facc[r][1] = 0.f; }
#pragma unroll 4
        for (int i = 0; i < EE; i++) {
            float2 wv = *(const float2*)(smf + F_W + i * DMOUT + 2 * lane);
            float a0 = smf[F_SO + (wid * 3 + 0) * SO + i];
            float a1 = smf[F_SO + (wid * 3 + 1) * SO + i];
            float a2 = smf[F_SO + (wid * 3 + 2) * SO + i];
            facc[0][0] += a0 * wv.x; facc[0][1] += a0 * wv.y;
            facc[1][0] += a1 * wv.x; facc[1][1] += a1 * wv.y;
            facc[2][0] += a2 * wv.x; facc[2][1] += a2 * wv.y;
        }
        float bb0 = smf[F_BIAS + 2 * lane], bb1 = smf[F_BIAS + 2 * lane + 1];
#pragma unroll
        for (int r = 0; r < 3; r++) {
            int t = wid * 3 + r;
            float* op = out + ((bn * TT) + t) * DMOUT + 2 * lane;
            *(float2*)op = make_float2(fmaxf(facc[r][0] + bb0, 0.f), fmaxf(facc[r][1] + bb1, 0.f));
        }
    }
}

// ---------------- launch ----------------
extern "C" void kernel_launch(void* const* d_in, const int* in_sizes, int n_in,
                              void* d_out, int out_size) {
    const float* query = (const float*)d_in[0];
    const float* key_  = (const float*)d_in[1];
    const float* value = (const float*)d_in[2];
    const float* qp1 = (const float*)d_in[4];
    const float* qp2 = (const float*)d_in[5];
    const float* kp1 = (const float*)d_in[6];
    const float* kp2 = (const float*)d_in[7];
    const float* vp1 = (const float*)d_in[8];
    const float* vp2 = (const float*)d_in[9];
    const float* outW = (const float*)d_in[10];
    const float* outb = (const float*)d_in[11];

    float* out = (float*)d_out;
    int write_attn = (out_size >= OUT_N + ATTN_N) ? 1 : 0;

    static int attr_done = 0;
    if (!attr_done) {
        cudaFuncSetAttribute(prep_P_kernel, cudaFuncAttributeMaxDynamicSharedMemorySize, 41216);
        cudaFuncSetAttribute(fused_kernel, cudaFuncAttributeMaxDynamicSharedMemorySize,
                             SMEMF_TOTAL * (int)sizeof(float));
        attr_done = 1;
    }

    prep_P_kernel<<<dim3(NN, 3), 256, 41216>>>(qp1, qp2, kp1, kp2, vp1, vp2);
    fused_kernel<<<dim3(BB, NN), 256, SMEMF_TOTAL * sizeof(float)>>>(
        query, key_, value, outW, outb, out, out + OUT_N, write_attn);
}

// round 6
// speedup vs baseline: 2.3241x; 1.2323x over previous
#include <cuda_runtime.h>
#include <cuda_fp16.h>
#include <cstdint>

// ---------------- problem constants ----------------
#define BB 32
#define NN 207
#define TT 24
#define EE 128
#define HH 8
#define HD 16
#define DMOUT 64
#define MM 32
#define G8 8                         // batches per fused block

#define OUT_N (BB * NN * TT * DMOUT)
#define ATTN_N (BB * NN * HH * TT * TT)

// P images: per (m,n): 128 k-rows x 128 n-cols fp16, swizzled (32KB)
__device__ __align__(16) __half g_Pimg[(size_t)3 * NN * 16384];

// ---------------- helpers ----------------
__device__ __forceinline__ uint32_t smem_u32(const void* p) {
    uint32_t a;
    asm("{ .reg .u64 t; cvta.to.shared.u64 t, %1; cvt.u32.u64 %0, t; }" : "=r"(a) : "l"(p));
    return a;
}
// swizzled byte offset: 256B rows, 16B chunks ci 0..15
__device__ __forceinline__ uint32_t sw_off(int r, int ci) {
    return (uint32_t)r * 256u + (uint32_t)((ci ^ (r & 7)) << 4);
}
__device__ __forceinline__ void ldsm_x4(uint32_t* r, uint32_t addr) {
    asm volatile("ldmatrix.sync.aligned.m8n8.x4.shared.b16 {%0,%1,%2,%3}, [%4];"
                 : "=r"(r[0]), "=r"(r[1]), "=r"(r[2]), "=r"(r[3]) : "r"(addr));
}
__device__ __forceinline__ void ldsm_x4_t(uint32_t* r, uint32_t addr) {
    asm volatile("ldmatrix.sync.aligned.m8n8.x4.trans.shared.b16 {%0,%1,%2,%3}, [%4];"
                 : "=r"(r[0]), "=r"(r[1]), "=r"(r[2]), "=r"(r[3]) : "r"(addr));
}
__device__ __forceinline__ void mma_f16(float* d, const uint32_t* a, const uint32_t* b) {
    asm volatile("mma.sync.aligned.m16n8k16.row.col.f32.f16.f16.f32 "
                 "{%0,%1,%2,%3}, {%4,%5,%6,%7}, {%8,%9}, {%0,%1,%2,%3};"
                 : "+f"(d[0]), "+f"(d[1]), "+f"(d[2]), "+f"(d[3])
                 : "r"(a[0]), "r"(a[1]), "r"(a[2]), "r"(a[3]), "r"(b[0]), "r"(b[1]));
}
#define CP_ASYNC16(dst, src) \
    asm volatile("cp.async.cg.shared.global [%0], [%1], 16;" :: "r"(dst), "l"(src))
#define CP_COMMIT() asm volatile("cp.async.commit_group;")
#define CP_WAIT0()  asm volatile("cp.async.wait_group 0;")

// ---------------- kernel 0: build P images (fp16, swizzled) ----------------
__global__ __launch_bounds__(256, 4) void prep_P_kernel(
    const float* __restrict__ qp1, const float* __restrict__ qp2,
    const float* __restrict__ kp1, const float* __restrict__ kp2,
    const float* __restrict__ vp1, const float* __restrict__ vp2) {
    extern __shared__ float sm0[];
    float* sp1 = sm0;              // 64 x 33 (padded)
    float* sp2 = sm0 + 2112;       // 32 x 256

    const int n = blockIdx.x, m = blockIdx.y, tid = threadIdx.x;
    const float* p1 = (m == 0) ? qp1 : ((m == 1) ? kp1 : vp1);
    const float* p2 = (m == 0) ? qp2 : ((m == 1) ? kp2 : vp2);

    for (int idx = tid; idx < 2048; idx += 256)
        sp1[(idx >> 5) * 33 + (idx & 31)] = p1[(size_t)n * 2048 + idx];
    for (int i = tid; i < 2048; i += 256)
        ((float4*)sp2)[i] = ((const float4*)p2)[i];
    __syncthreads();

    char* gbase = (char*)(g_Pimg + (size_t)(m * NN + n) * 16384);
    const float4* sp2f4 = (const float4*)sp2;
#pragma unroll
    for (int it = 0; it < 16; it++) {
        int idx = it * 256 + tid;                  // 4096 float4 jobs
        int group = idx >> 5, l = idx & 31;
        int c4 = (group & 7) * 4 + (l & 3);        // 0..31
        int k  = (group >> 3) * 8 + (l >> 2);      // 0..127
        const float* a = sp1 + (k >> 1) * 33;
        int boff = (k & 1) * 32 + c4;
        float4 acc = make_float4(0.f, 0.f, 0.f, 0.f);
#pragma unroll
        for (int j = 0; j < 32; j++) {
            float aj = a[j];
            float4 bv = sp2f4[j * 64 + boff];
            acc.x += aj * bv.x; acc.y += aj * bv.y; acc.z += aj * bv.z; acc.w += aj * bv.w;
        }
        __half2 p01 = __float22half2_rn(make_float2(acc.x, acc.y));
        __half2 p23 = __float22half2_rn(make_float2(acc.z, acc.w));
        uint2 pk;
        pk.x = *(uint32_t*)&p01; pk.y = *(uint32_t*)&p23;
        uint32_t off = sw_off(k, c4 >> 1) + (uint32_t)(c4 & 1) * 8u;
        *(uint2*)(gbase + off) = pk;
    }
}

// ---------------- fused kernel: 8 batches per block ----------------
// smem bytes:
//  [A 0..49152)   192x128 fp16 swizzled
//  [B 49152..81920) 128x128 fp16 swizzled P image
//  [QKV 81920..231680) fp16 [m][g][t] rows of 130 halves (260B)
// post-GEMM reuse of A+B region: W @0 (32KB), bias @32768, sO slots @33024 (2 x 24x132 f32)
#define OFF_Bb 49152
#define OFF_QKV 81920
#define QKV_OFF(m, g, t) (OFF_QKV + (((m) * G8 + (g)) * TT + (t)) * 260)
#define OFF_BIAS 32768
#define OFF_SO 33024
#define SO_SLOT 12672
#define SMEMF_TOTAL 231680

__global__ __launch_bounds__(512, 1) void fused_kernel(
    const float* __restrict__ query, const float* __restrict__ key_,
    const float* __restrict__ value,
    const float* __restrict__ outW, const float* __restrict__ outb,
    float* __restrict__ out, float* __restrict__ attn_out, int write_attn) {
    extern __shared__ float smf[];
    char* smb = (char*)smf;
    const uint32_t sbase = smem_u32(smb);

    const int n = blockIdx.x;
    const int b0 = blockIdx.y * G8;
    const int tid = threadIdx.x, wid = tid >> 5, lane = tid & 31;
    const int wr = wid >> 2, wc = wid & 3;        // warp grid 4(M) x 4(N)
    const int grp = lane >> 2, tid4 = lane & 3;
    const int lq = lane & 7, qq = lane >> 3;

    // ===== three projections (M=192 = 8 batches x 24) =====
    for (int m = 0; m < 3; m++) {
        if (m) __syncthreads();
        // B: async copy P image (32KB)
        {
            const char* bs = (const char*)(g_Pimg + (size_t)(m * NN + n) * 16384);
            uint32_t bd = sbase + OFF_Bb;
#pragma unroll
            for (int i = 0; i < 4; i++) {
                int c = i * 512 + tid;
                CP_ASYNC16(bd + c * 16, bs + c * 16);
            }
            CP_COMMIT();
        }
        // A: 192 rows x 128 fp32 -> fp16 swizzled
        {
            const float* x = (m == 0) ? query : ((m == 1) ? key_ : value);
#pragma unroll
            for (int it = 0; it < 12; it++) {
                int idx = it * 512 + tid;          // 6144 float4 jobs
                int r = idx >> 5, c4 = idx & 31;
                int g = r / TT, t = r - g * TT;
                float4 v = *(const float4*)(x + (((size_t)(b0 + g) * NN + n) * TT + t) * EE + 4 * c4);
                __half2 p01 = __float22half2_rn(make_float2(v.x, v.y));
                __half2 p23 = __float22half2_rn(make_float2(v.z, v.w));
                uint2 pk;
                pk.x = *(uint32_t*)&p01; pk.y = *(uint32_t*)&p23;
                uint32_t off = sw_off(r, c4 >> 1) + (uint32_t)(c4 & 1) * 8u;
                *(uint2*)(smb + off) = pk;
            }
        }
        CP_WAIT0();
        __syncthreads();

        // GEMM 192 x 128 x 128, single pass fp16
        float acc[3][4][4];
#pragma unroll
        for (int mr = 0; mr < 3; mr++)
#pragma unroll
            for (int nt = 0; nt < 4; nt++)
#pragma unroll
                for (int i = 0; i < 4; i++) acc[mr][nt][i] = 0.f;

#pragma unroll
        for (int kc = 0; kc < 8; kc++) {
            uint32_t a[3][4];
#pragma unroll
            for (int mr = 0; mr < 3; mr++) {
                int r = wr * 48 + mr * 16 + lq + (qq & 1) * 8;
                int ci = kc * 2 + (qq >> 1);
                ldsm_x4(a[mr], sbase + sw_off(r, ci));
            }
            uint32_t bf[4][2];
#pragma unroll
            for (int p = 0; p < 2; p++) {
                int r = kc * 16 + lq + (qq & 1) * 8;
                int ci = wc * 4 + p * 2 + (qq >> 1);
                uint32_t t4[4];
                ldsm_x4_t(t4, sbase + OFF_Bb + sw_off(r, ci));
                bf[2 * p][0] = t4[0]; bf[2 * p][1] = t4[1];
                bf[2 * p + 1][0] = t4[2]; bf[2 * p + 1][1] = t4[3];
            }
#pragma unroll
            for (int mr = 0; mr < 3; mr++)
#pragma unroll
                for (int nt = 0; nt < 4; nt++)
                    mma_f16(acc[mr][nt], a[mr], bf[nt]);
        }

        // epilogue: relu -> qkv fp16
#pragma unroll
        for (int mr = 0; mr < 3; mr++) {
#pragma unroll
            for (int half = 0; half < 2; half++) {
                int row = wr * 48 + mr * 16 + half * 8 + grp;
                int g = row / TT, t = row - g * TT;
                char* dst = smb + QKV_OFF(m, g, t);
#pragma unroll
                for (int nt = 0; nt < 4; nt++) {
                    int col = wc * 32 + nt * 8 + tid4 * 2;
                    __half2 hv = __float22half2_rn(make_float2(
                        fmaxf(acc[mr][nt][half * 2 + 0], 0.f),
                        fmaxf(acc[mr][nt][half * 2 + 1], 0.f)));
                    *(uint32_t*)(dst + col * 2) = *(uint32_t*)&hv;
                }
            }
        }
    }
    __syncthreads();      // qkv complete; A+B regions free

    // W + bias async copy (overlaps attention)
    {
        const char* ws = (const char*)outW;
#pragma unroll
        for (int i = 0; i < 4; i++) {
            int c = i * 512 + tid;
            CP_ASYNC16(sbase + c * 16, ws + c * 16);
        }
        if (tid < 16) CP_ASYNC16(sbase + OFF_BIAS + tid * 16, ((const char*)outb) + tid * 16);
        CP_COMMIT();
    }

    // ===== attention + output proj: 4 reps x 2 batches =====
    for (int rep = 0; rep < 4; rep++) {
        if (rep) __syncthreads();    // prev rep's proj done reading sO
        const int slot = wid >> 3, h = wid & 7;
        const int gg = rep * 2 + slot;
        const long bn = (long)(b0 + gg) * NN + n;
        const int t = lane;
        if (t < TT) {
            float qr[HD];
            {
                const uint32_t* qp = (const uint32_t*)(smb + QKV_OFF(0, gg, t) + h * 32);
#pragma unroll
                for (int e2 = 0; e2 < 8; e2++) {
                    uint32_t u = qp[e2];
                    float2 f = __half22float2(*(const __half2*)&u);
                    qr[2 * e2] = f.x; qr[2 * e2 + 1] = f.y;
                }
            }
            float sc[TT];
#pragma unroll
            for (int s = 0; s < TT; s++) {
                const uint32_t* kp = (const uint32_t*)(smb + QKV_OFF(1, gg, s) + h * 32);
                float a = 0.f;
#pragma unroll
                for (int e2 = 0; e2 < 8; e2++) {
                    uint32_t u = kp[e2];
                    float2 f = __half22float2(*(const __half2*)&u);
                    a += qr[2 * e2] * f.x + qr[2 * e2 + 1] * f.y;
                }
                sc[s] = a;
            }
            const float scale = 0.25f;
            float mx = -1e30f;
#pragma unroll
            for (int s = 0; s < TT; s++) if (s <= t) mx = fmaxf(mx, sc[s] * scale);
            float sum = 0.f, pr[TT];
#pragma unroll
            for (int s = 0; s < TT; s++) {
                float p = (s <= t) ? __expf(sc[s] * scale - mx) : 0.f;
                pr[s] = p; sum += p;
            }
            float inv = 1.f / sum;
#pragma unroll
            for (int s = 0; s < TT; s++) pr[s] *= inv;

            float o[HD];
#pragma unroll
            for (int d = 0; d < HD; d++) o[d] = 0.f;
#pragma unroll
            for (int s = 0; s < TT; s++) {
                const uint32_t* vp = (const uint32_t*)(smb + QKV_OFF(2, gg, s) + h * 32);
                float pv = pr[s];
#pragma unroll
                for (int d2 = 0; d2 < 8; d2++) {
                    uint32_t u = vp[d2];
                    float2 f = __half22float2(*(const __half2*)&u);
                    o[2 * d2] += pv * f.x; o[2 * d2 + 1] += pv * f.y;
                }
            }
            float* so = smf + (OFF_SO / 4) + slot * (SO_SLOT / 4) + t * 132 + h * HD;
#pragma unroll
            for (int d = 0; d < HD; d += 2)
                *(float2*)(so + d) = make_float2(o[d], o[d + 1]);

            if (write_attn) {
                float* ab = attn_out + (((bn * HH) + h) * TT + t) * TT;
#pragma unroll
                for (int s4 = 0; s4 < TT / 4; s4++)
                    ((float4*)ab)[s4] = make_float4(pr[4 * s4], pr[4 * s4 + 1], pr[4 * s4 + 2], pr[4 * s4 + 3]);
            }
        }
        if (rep == 0) CP_WAIT0();
        __syncthreads();   // sO ready, W ready

        // output proj: slot's 8 warps handle 24 rows (3 each)
        {
            const int w8 = wid & 7;
            const float* soB = smf + (OFF_SO / 4) + slot * (SO_SLOT / 4);
            float facc[3][2];
#pragma unroll
            for (int r = 0; r < 3; r++) { facc[r][0] = 0.f; facc[r][1] = 0.f; }
#pragma unroll 4
            for (int i = 0; i < EE; i++) {
                float2 wv = *(const float2*)(smf + i * DMOUT + 2 * lane);
                float a0 = soB[(w8 * 3 + 0) * 132 + i];
                float a1 = soB[(w8 * 3 + 1) * 132 + i];
                float a2 = soB[(w8 * 3 + 2) * 132 + i];
                facc[0][0] += a0 * wv.x; facc[0][1] += a0 * wv.y;
                facc[1][0] += a1 * wv.x; facc[1][1] += a1 * wv.y;
                facc[2][0] += a2 * wv.x; facc[2][1] += a2 * wv.y;
            }
            float bb0 = smf[OFF_BIAS / 4 + 2 * lane], bb1 = smf[OFF_BIAS / 4 + 2 * lane + 1];
#pragma unroll
            for (int r = 0; r < 3; r++) {
                int trow = w8 * 3 + r;
                float* op = out + ((bn * TT) + trow) * DMOUT + 2 * lane;
                *(float2*)op = make_float2(fmaxf(facc[r][0] + bb0, 0.f), fmaxf(facc[r][1] + bb1, 0.f));
            }
        }
    }
}

// ---------------- launch ----------------
extern "C" void kernel_launch(void* const* d_in, const int* in_sizes, int n_in,
                              void* d_out, int out_size) {
    const float* query = (const float*)d_in[0];
    const float* key_  = (const float*)d_in[1];
    const float* value = (const float*)d_in[2];
    const float* qp1 = (const float*)d_in[4];
    const float* qp2 = (const float*)d_in[5];
    const float* kp1 = (const float*)d_in[6];
    const float* kp2 = (const float*)d_in[7];
    const float* vp1 = (const float*)d_in[8];
    const float* vp2 = (const float*)d_in[9];
    const float* outW = (const float*)d_in[10];
    const float* outb = (const float*)d_in[11];

    float* out = (float*)d_out;
    int write_attn = (out_size >= OUT_N + ATTN_N) ? 1 : 0;

    static int attr_done = 0;
    if (!attr_done) {
        cudaFuncSetAttribute(prep_P_kernel, cudaFuncAttributeMaxDynamicSharedMemorySize, 41216);
        cudaFuncSetAttribute(fused_kernel, cudaFuncAttributeMaxDynamicSharedMemorySize, SMEMF_TOTAL);
        attr_done = 1;
    }

    prep_P_kernel<<<dim3(NN, 3), 256, 41216>>>(qp1, qp2, kp1, kp2, vp1, vp2);
    fused_kernel<<<dim3(NN, BB / G8), 512, SMEMF_TOTAL>>>(
        query, key_, value, outW, outb, out, out + OUT_N, write_attn);
}